// round 6
// baseline (speedup 1.0000x reference)
#include <cuda_runtime.h>
#include <cstdint>

// B=8, S=512, V=32000, D=4096, r=16, E=4
#define TOKS   4096
#define SLEN   512
#define SPLITL 32
#define DDIM   4096
#define VDIM   32000
#define SCALE  2.0f   // lora_alpha / r

#define TTOK   64     // tokens per tile
#define TD     256    // d per tile (128 threads * d-span 2)
#define CPAD   36     // padded c-row stride in floats
#define RING   16     // cp.async pipeline depth (tokens)

typedef unsigned long long u64;

__device__ __forceinline__ void upk2(u64 v, float& lo, float& hi) {
    asm("mov.b64 {%0, %1}, %2;" : "=f"(lo), "=f"(hi) : "l"(v));
}
__device__ __forceinline__ u64 add2(u64 a, u64 b) {
    u64 r; asm("add.rn.f32x2 %0, %1, %2;" : "=l"(r) : "l"(a), "l"(b)); return r;
}
__device__ __forceinline__ void fma2(u64& acc, u64 a, u64 b) {
    asm("fma.rn.f32x2 %0, %1, %2, %0;" : "+l"(acc) : "l"(a), "l"(b));
}
__device__ __forceinline__ uint32_t s2u(const void* p) {
    uint32_t a;
    asm("{ .reg .u64 t; cvta.to.shared.u64 t, %1; cvt.u32.u64 %0, t; }"
        : "=r"(a) : "l"(p));
    return a;
}

// ---------------------------------------------------------------------------
// Grid (64 token-tiles, 16 d-tiles) = 1024 CTAs, 128 threads, 4 CTAs/SM.
// Thread owns d-pair (d0,d0+1); k packed PAIRWISE into f32x2 (B pairs are raw
// contiguous row loads; c rows plain floats in smem; 8 broadcast LDS.128 feed
// 32 fma2 per token). Base-row gather is a 16-deep cp.async ring: thread i
// stages exactly the 8B it later reads; one commit group per token;
// wait_group 15 retires token t at iteration t. Prologue (16 tokens) is
// issued before the c-phase so DRAM latency hides behind the A/W gathers.
// int64/int32 x detection: odd words of first 256 x-words all zero <=> int64.
// ---------------------------------------------------------------------------
__global__ __launch_bounds__(128, 4) void fused_k(
    const int*   __restrict__ xw,
    const float* __restrict__ emb,
    const float* __restrict__ A1, const float* __restrict__ B1,
    const float* __restrict__ A2, const float* __restrict__ B2,
    const float* __restrict__ Wi, const float* __restrict__ bi,
    const float* __restrict__ Wt, const float* __restrict__ bt,
    float* __restrict__ out)
{
    __shared__ __align__(16) float scf[TTOK * CPAD];   // c[t][k]
    __shared__ __align__(16) float sbase[RING][TD];    // staged base rows
    __shared__ int      stok[TTOK];
    __shared__ unsigned sdet[4];

    const int tid   = threadIdx.x;
    const int ttile = blockIdx.x;
    const int d0    = blockIdx.y * TD + tid * 2;

    // --- dtype detect ---
    {
        int hiw = xw[2 * tid + 1];                    // words 1..255, in-bounds both ways
        unsigned ball = __ballot_sync(0xffffffffu, hiw != 0);
        if ((tid & 31) == 0) sdet[tid >> 5] = ball;
    }

    // --- B rows straight into u64 pairs: Bp{A,B}[j] = {B[d,2j],B[d,2j+1]} ---
    u64 BpA[16], BpB[16];
    {
        const ulonglong2* r;
        r = (const ulonglong2*)(B1 + (size_t)(d0 + 0) * 16);
#pragma unroll
        for (int q = 0; q < 4; q++) { ulonglong2 v = r[q]; BpA[2*q] = v.x; BpA[2*q+1] = v.y; }
        r = (const ulonglong2*)(B2 + (size_t)(d0 + 0) * 16);
#pragma unroll
        for (int q = 0; q < 4; q++) { ulonglong2 v = r[q]; BpA[8+2*q] = v.x; BpA[8+2*q+1] = v.y; }
        r = (const ulonglong2*)(B1 + (size_t)(d0 + 1) * 16);
#pragma unroll
        for (int q = 0; q < 4; q++) { ulonglong2 v = r[q]; BpB[2*q] = v.x; BpB[2*q+1] = v.y; }
        r = (const ulonglong2*)(B2 + (size_t)(d0 + 1) * 16);
#pragma unroll
        for (int q = 0; q < 4; q++) { ulonglong2 v = r[q]; BpB[8+2*q] = v.x; BpB[8+2*q+1] = v.y; }
    }
    __syncthreads();                                   // sdet visible

    const bool is64 = ((sdet[0] | sdet[1] | sdet[2] | sdet[3]) == 0);
    if (tid < TTOK) {
        const int i = ttile * TTOK + tid;
        stok[tid] = is64 ? xw[2 * i] : xw[i];
    }
    __syncthreads();                                   // stok visible

    // --- prologue: stage first RING base rows via cp.async (8B per thread) ---
    const uint32_t myoff = (uint32_t)tid * 8u;         // byte offset within a row
#pragma unroll
    for (int s = 0; s < RING; s++) {
        const float* src = emb + (size_t)stok[s] * DDIM + d0;
        uint32_t dst = s2u(&sbase[s][0]) + myoff;
        asm volatile("cp.async.ca.shared.global [%0], [%1], 8;\n\t"
                     "cp.async.commit_group;"
                     :: "r"(dst), "l"(src) : "memory");
    }

    // --- c phase: half 0 -> A1 (k 0..15), half 1 -> A2 (k 16..31) ---
    {
        const int  half = tid >> 6;
        const int  t    = tid & 63;
        const int  i    = ttile * TTOK + t;
        const int  tok  = stok[t];
        const int  s    = i & (SLEN - 1);
        const float* W  = (s < SPLITL) ? Wi : Wt;
        const float* b  = (s < SPLITL) ? bi : bt;
        float l0 = W[tok] + b[0];
        float l1 = W[VDIM + tok] + b[1];
        float w0 = 1.0f / (1.0f + expf(l1 - l0));
        float sA = half ? (SCALE - w0 * SCALE) : (w0 * SCALE);
        const float* Am = half ? A2 : A1;
        float c[16];
#pragma unroll
        for (int r = 0; r < 16; r++) c[r] = sA * Am[(size_t)r * VDIM + tok];
        float4* dst = (float4*)(scf + t * CPAD + half * 16);
#pragma unroll
        for (int q = 0; q < 4; q++)
            dst[q] = make_float4(c[4*q], c[4*q+1], c[4*q+2], c[4*q+3]);
    }
    __syncthreads();                                   // scf visible

    // --- main loop over 64 tokens; ring keeps 16 tokens in flight ---
    const size_t ob = (size_t)(ttile * TTOK) * DDIM + d0;

#pragma unroll 1
    for (int t = 0; t < TTOK; t++) {
        // retire token t (all but the newest 15 groups complete)
        asm volatile("cp.async.wait_group 15;" ::: "memory");

        float2 bv = *(const float2*)((const char*)&sbase[t & (RING - 1)][0] + myoff);

        const ulonglong2* cr = (const ulonglong2*)(scf + t * CPAD);
        u64 aA0 = 0ull, aA1 = 0ull, aB0 = 0ull, aB1 = 0ull;
#pragma unroll
        for (int jj = 0; jj < 8; jj++) {
            ulonglong2 cc = cr[jj];                    // LDS.128 broadcast
            fma2(aA0, BpA[2*jj],     cc.x);
            fma2(aA1, BpA[2*jj + 1], cc.y);
            fma2(aB0, BpB[2*jj],     cc.x);
            fma2(aB1, BpB[2*jj + 1], cc.y);
        }
        u64 sA = add2(aA0, aA1);
        u64 sB = add2(aB0, aB1);
        float alo, ahi, blo, bhi;
        upk2(sA, alo, ahi);
        upk2(sB, blo, bhi);
        float2 o;
        o.x = bv.x + (alo + ahi);
        o.y = bv.y + (blo + bhi);
        __stcs((float2*)(out + ob + (size_t)t * DDIM), o);

        // refill the slot just consumed with token t+RING (or an empty group
        // to keep per-thread group counting aligned with wait_group 15)
        if (t + RING < TTOK) {
            const float* src = emb + (size_t)stok[t + RING] * DDIM + d0;
            uint32_t dst = s2u(&sbase[t & (RING - 1)][0]) + myoff;
            asm volatile("cp.async.ca.shared.global [%0], [%1], 8;\n\t"
                         "cp.async.commit_group;"
                         :: "r"(dst), "l"(src) : "memory");
        } else {
            asm volatile("cp.async.commit_group;" ::: "memory");
        }
    }
}

// ---------------------------------------------------------------------------
extern "C" void kernel_launch(void* const* d_in, const int* in_sizes, int n_in,
                              void* d_out, int out_size) {
    const int*   x   = (const int*)d_in[0];
    const float* emb = (const float*)d_in[1];
    const float* A1  = (const float*)d_in[2];
    const float* B1  = (const float*)d_in[3];
    const float* A2  = (const float*)d_in[4];
    const float* B2  = (const float*)d_in[5];
    const float* Wi  = (const float*)d_in[6];
    const float* bi  = (const float*)d_in[7];
    const float* Wt  = (const float*)d_in[8];
    const float* bt  = (const float*)d_in[9];
    float* out = (float*)d_out;

    fused_k<<<dim3(TOKS / TTOK, DDIM / TD), 128>>>(
        x, emb, A1, B1, A2, B2, Wi, bi, Wt, bt, out);
}

// round 7
// speedup vs baseline: 1.0112x; 1.0112x over previous
#include <cuda_runtime.h>
#include <cstdint>

// B=8, S=512, V=32000, D=4096, r=16, E=4
#define TOKS   4096
#define SLEN   512
#define SPLITL 32
#define DDIM   4096
#define VDIM   32000
#define SCALE  2.0f   // lora_alpha / r

#define TTOK   64     // tokens per tile
#define TD     512    // d per tile (128 threads * d-span 4)
#define CPAD   36     // padded c-row stride in floats

typedef unsigned long long u64;

__device__ __forceinline__ void upk2(u64 v, float& lo, float& hi) {
    asm("mov.b64 {%0, %1}, %2;" : "=f"(lo), "=f"(hi) : "l"(v));
}
__device__ __forceinline__ u64 add2(u64 a, u64 b) {
    u64 r; asm("add.rn.f32x2 %0, %1, %2;" : "=l"(r) : "l"(a), "l"(b)); return r;
}
__device__ __forceinline__ void fma2(u64& acc, u64 a, u64 b) {
    asm("fma.rn.f32x2 %0, %1, %2, %0;" : "+l"(acc) : "l"(a), "l"(b));
}

// ---------------------------------------------------------------------------
// Grid (64 token-tiles, 8 d-tiles) = 512 CTAs, 128 threads, 2 CTAs/SM.
// Thread owns 4 consecutive d's. k packed PAIRWISE into f32x2: B pairs
// {B[d,2j],B[d,2j+1]} are raw contiguous row loads (4 d's x 16 pairs = 128
// regs); c rows are plain floats in smem. Per token per warp: 8 broadcast
// LDS.128 feed 64 fma2 -> 128 outputs (2x fewer LDS/output than d-span 2).
// Base gather: register prefetch depth 4, LDG.128. Streaming STG.128.
// c-phase: threads 0-63 do A1 (k 0..15), 64-127 do A2 (k 16..31).
// int64/int32 x detection: odd words of first 256 x-words all zero <=> int64.
// ---------------------------------------------------------------------------
__global__ __launch_bounds__(128, 2) void fused_k(
    const int*   __restrict__ xw,
    const float* __restrict__ emb,
    const float* __restrict__ A1, const float* __restrict__ B1,
    const float* __restrict__ A2, const float* __restrict__ B2,
    const float* __restrict__ Wi, const float* __restrict__ bi,
    const float* __restrict__ Wt, const float* __restrict__ bt,
    float* __restrict__ out)
{
    __shared__ __align__(16) float scf[TTOK * CPAD];   // c[t][k]
    __shared__ int      stok[TTOK];
    __shared__ unsigned sdet[4];

    const int tid   = threadIdx.x;
    const int ttile = blockIdx.x;
    const int d0    = blockIdx.y * TD + tid * 4;

    // --- dtype detect ---
    {
        int hiw = xw[2 * tid + 1];                    // words 1..255, in-bounds both ways
        unsigned ball = __ballot_sync(0xffffffffu, hiw != 0);
        if ((tid & 31) == 0) sdet[tid >> 5] = ball;
    }

    // --- B rows for d0..d0+3 straight into u64 k-pairs ---
    u64 BpA[16], BpB[16], BpC[16], BpD[16];
    {
        const ulonglong2* r;
        r = (const ulonglong2*)(B1 + (size_t)(d0 + 0) * 16);
#pragma unroll
        for (int q = 0; q < 4; q++) { ulonglong2 v = r[q]; BpA[2*q] = v.x; BpA[2*q+1] = v.y; }
        r = (const ulonglong2*)(B2 + (size_t)(d0 + 0) * 16);
#pragma unroll
        for (int q = 0; q < 4; q++) { ulonglong2 v = r[q]; BpA[8+2*q] = v.x; BpA[8+2*q+1] = v.y; }
        r = (const ulonglong2*)(B1 + (size_t)(d0 + 1) * 16);
#pragma unroll
        for (int q = 0; q < 4; q++) { ulonglong2 v = r[q]; BpB[2*q] = v.x; BpB[2*q+1] = v.y; }
        r = (const ulonglong2*)(B2 + (size_t)(d0 + 1) * 16);
#pragma unroll
        for (int q = 0; q < 4; q++) { ulonglong2 v = r[q]; BpB[8+2*q] = v.x; BpB[8+2*q+1] = v.y; }
        r = (const ulonglong2*)(B1 + (size_t)(d0 + 2) * 16);
#pragma unroll
        for (int q = 0; q < 4; q++) { ulonglong2 v = r[q]; BpC[2*q] = v.x; BpC[2*q+1] = v.y; }
        r = (const ulonglong2*)(B2 + (size_t)(d0 + 2) * 16);
#pragma unroll
        for (int q = 0; q < 4; q++) { ulonglong2 v = r[q]; BpC[8+2*q] = v.x; BpC[8+2*q+1] = v.y; }
        r = (const ulonglong2*)(B1 + (size_t)(d0 + 3) * 16);
#pragma unroll
        for (int q = 0; q < 4; q++) { ulonglong2 v = r[q]; BpD[2*q] = v.x; BpD[2*q+1] = v.y; }
        r = (const ulonglong2*)(B2 + (size_t)(d0 + 3) * 16);
#pragma unroll
        for (int q = 0; q < 4; q++) { ulonglong2 v = r[q]; BpD[8+2*q] = v.x; BpD[8+2*q+1] = v.y; }
    }
    __syncthreads();                                   // sdet visible

    // --- c phase: half 0 -> A1 (k 0..15), half 1 -> A2 (k 16..31) ---
    {
        const bool is64 = ((sdet[0] | sdet[1] | sdet[2] | sdet[3]) == 0);
        const int  half = tid >> 6;
        const int  t    = tid & 63;
        const int  i    = ttile * TTOK + t;
        const int  tok  = is64 ? xw[2 * i] : xw[i];
        if (half == 0) stok[t] = tok;
        const int s = i & (SLEN - 1);
        const float* W = (s < SPLITL) ? Wi : Wt;
        const float* b = (s < SPLITL) ? bi : bt;
        float l0 = W[tok] + b[0];
        float l1 = W[VDIM + tok] + b[1];
        float w0 = 1.0f / (1.0f + expf(l1 - l0));
        float sA = half ? (SCALE - w0 * SCALE) : (w0 * SCALE);
        const float* Am = half ? A2 : A1;
        float c[16];
#pragma unroll
        for (int r = 0; r < 16; r++) c[r] = sA * Am[(size_t)r * VDIM + tok];
        float4* dst = (float4*)(scf + t * CPAD + half * 16);
#pragma unroll
        for (int q = 0; q < 4; q++)
            dst[q] = make_float4(c[4*q], c[4*q+1], c[4*q+2], c[4*q+3]);
    }
    __syncthreads();                                   // scf visible

    // --- main loop over 64 tokens, register prefetch depth 4, LDG.128 ---
    const size_t ob = (size_t)(ttile * TTOK) * DDIM + d0;
    float4 pf[4];
#pragma unroll
    for (int j = 0; j < 4; j++)
        pf[j] = __ldg((const float4*)(emb + (size_t)stok[j] * DDIM + d0));

#pragma unroll 1
    for (int t0 = 0; t0 < TTOK; t0 += 4) {
        float4 cur[4];
#pragma unroll
        for (int j = 0; j < 4; j++) cur[j] = pf[j];
        if (t0 + 4 < TTOK) {
#pragma unroll
            for (int j = 0; j < 4; j++)
                pf[j] = __ldg((const float4*)(emb + (size_t)stok[t0 + 4 + j] * DDIM + d0));
        }
#pragma unroll
        for (int j = 0; j < 4; j++) {
            const int t = t0 + j;
            const ulonglong2* cr = (const ulonglong2*)(scf + t * CPAD);
            u64 aA0 = 0, aA1 = 0, aB0 = 0, aB1 = 0;
            u64 aC0 = 0, aC1 = 0, aD0 = 0, aD1 = 0;
#pragma unroll
            for (int jj = 0; jj < 8; jj++) {
                ulonglong2 cc = cr[jj];                // LDS.128 broadcast
                fma2(aA0, BpA[2*jj],     cc.x);
                fma2(aA1, BpA[2*jj + 1], cc.y);
                fma2(aB0, BpB[2*jj],     cc.x);
                fma2(aB1, BpB[2*jj + 1], cc.y);
                fma2(aC0, BpC[2*jj],     cc.x);
                fma2(aC1, BpC[2*jj + 1], cc.y);
                fma2(aD0, BpD[2*jj],     cc.x);
                fma2(aD1, BpD[2*jj + 1], cc.y);
            }
            u64 sA = add2(aA0, aA1);
            u64 sB = add2(aB0, aB1);
            u64 sC = add2(aC0, aC1);
            u64 sD = add2(aD0, aD1);
            float alo, ahi, blo, bhi, clo, chi, dlo, dhi;
            upk2(sA, alo, ahi);
            upk2(sB, blo, bhi);
            upk2(sC, clo, chi);
            upk2(sD, dlo, dhi);
            float4 o;
            o.x = cur[j].x + (alo + ahi);
            o.y = cur[j].y + (blo + bhi);
            o.z = cur[j].z + (clo + chi);
            o.w = cur[j].w + (dlo + dhi);
            __stcs((float4*)(out + ob + (size_t)t * DDIM), o);
        }
    }
}

// ---------------------------------------------------------------------------
extern "C" void kernel_launch(void* const* d_in, const int* in_sizes, int n_in,
                              void* d_out, int out_size) {
    const int*   x   = (const int*)d_in[0];
    const float* emb = (const float*)d_in[1];
    const float* A1  = (const float*)d_in[2];
    const float* B1  = (const float*)d_in[3];
    const float* A2  = (const float*)d_in[4];
    const float* B2  = (const float*)d_in[5];
    const float* Wi  = (const float*)d_in[6];
    const float* bi  = (const float*)d_in[7];
    const float* Wt  = (const float*)d_in[8];
    const float* bt  = (const float*)d_in[9];
    float* out = (float*)d_out;

    fused_k<<<dim3(TOKS / TTOK, DDIM / TD), 128>>>(
        x, emb, A1, B1, A2, B2, Wi, bi, Wt, bt, out);
}